// round 13
// baseline (speedup 1.0000x reference)
#include <cuda_runtime.h>
#include <math_constants.h>

#define BB 64
#define SS 512
#define TT 128
#define NT 128

__device__ float g_partial[BB];
__device__ unsigned int g_ctr = 0;

static __device__ __forceinline__ unsigned long long ffma2(unsigned long long a,
                                                           unsigned long long b,
                                                           unsigned long long c) {
    unsigned long long d;
    asm("fma.rn.f32x2 %0, %1, %2, %3;" : "=l"(d) : "l"(a), "l"(b), "l"(c));
    return d;
}
static __device__ __forceinline__ unsigned long long addf2(unsigned long long a,
                                                           unsigned long long b) {
    unsigned long long d;
    asm("add.rn.f32x2 %0, %1, %2;" : "=l"(d) : "l"(a), "l"(b));
    return d;
}
static __device__ __forceinline__ unsigned long long pack2(float x, float y) {
    unsigned long long d;
    asm("mov.b64 %0, {%1, %2};" : "=l"(d) : "f"(x), "f"(y));
    return d;
}
static __device__ __forceinline__ float2 unpack2(unsigned long long v) {
    float2 r;
    asm("mov.b64 {%0, %1}, %2;" : "=f"(r.x), "=f"(r.y) : "l"(v));
    return r;
}

__global__ __launch_bounds__(NT, 1)
void crf_kernel(const float* __restrict__ feats,
                const int* __restrict__ mask,
                const int* __restrict__ tags,
                const float* __restrict__ trans,
                const float* __restrict__ start_t,
                const float* __restrict__ stop_t,
                float* __restrict__ out)
{
    __shared__ __align__(16) float sh_q[2][TT];   // double-buffered linear partition
    __shared__ int sh_mk[SS];
    __shared__ float sh_wmax[4];
    __shared__ float sh_redf[4];
    __shared__ float sh_redl[4];
    __shared__ int sh_last;

    const int b = blockIdx.x;
    const int t = threadIdx.x;          // == column j
    const int j = t;
    const int wq = t >> 5;
    const int l = t & 31;
    const float* Fb = feats + (size_t)b * SS * TT;
    const int* Mk = mask + b * SS;
    const int* Tg = tags + b * SS;

    // preload mask into shared
    for (int s = t; s < SS; s += NT) sh_mk[s] = Mk[s];

    // E[i][j] = exp(trans[j][i]) for ALL i, this thread's column j
    unsigned long long e2[64];
#pragma unroll
    for (int k = 0; k < 64; k++) {
        float2 tv = *(const float2*)(trans + j * TT + 2 * k);
        e2[k] = pack2(__expf(tv.x), __expf(tv.y));
    }

    // ---- init: q0[j] = exp(F[0,j] + start[j]) ----
    float qj = __expf(Fb[j] + start_t[j]);
    sh_q[0][j] = qj;
    int Cexp = 0;
    float ef   = __expf(Fb[1 * TT + j]);
    float fnx  = Fb[2 * TT + j];
    float fnx2 = Fb[3 * TT + j];
    __syncthreads();

    // ---- sequential scan: 4-warp barrier, broadcast LDS, 8 accumulator chains ----
#pragma unroll 2
    for (int s = 1; s < SS; s++) {
        const int p = (s - 1) & 1;

        // phase A: exact pow2 normalizer + prefetch (off the matvec path)
        float q0p = sh_q[p][0];
        int e = (__float_as_int(q0p) >> 23) - 127;
        float rinv = __int_as_float((127 - e) << 23);
        Cexp += e;
        float sc = ef * rinv;
        float efn = __expf(fnx);
        int sp3 = (s + 3 < SS) ? (s + 3) : (SS - 1);
        float fnew = Fb[(size_t)sp3 * TT + j];
        int mcur = sh_mk[s];

        // phase B: FULL matvec for column j — 32 broadcast LDS.128, 64 ffma2,
        // 8 independent accumulator chains (depth 8 = 32 cyc latency tail)
        const ulonglong2* q8 = (const ulonglong2*)(&sh_q[p][0]);
        unsigned long long a0 = 0ull, a1 = 0ull, a2 = 0ull, a3 = 0ull;
        unsigned long long a4 = 0ull, a5 = 0ull, a6 = 0ull, a7 = 0ull;
#pragma unroll
        for (int k = 0; k < 32; k += 4) {
            ulonglong2 v0 = q8[k + 0], v1 = q8[k + 1], v2 = q8[k + 2], v3 = q8[k + 3];
            a0 = ffma2(e2[2 * k + 0], v0.x, a0);
            a1 = ffma2(e2[2 * k + 1], v0.y, a1);
            a2 = ffma2(e2[2 * k + 2], v1.x, a2);
            a3 = ffma2(e2[2 * k + 3], v1.y, a3);
            a4 = ffma2(e2[2 * k + 4], v2.x, a4);
            a5 = ffma2(e2[2 * k + 5], v2.y, a5);
            a6 = ffma2(e2[2 * k + 6], v3.x, a6);
            a7 = ffma2(e2[2 * k + 7], v3.y, a7);
        }
        unsigned long long s01 = addf2(a0, a1), s23 = addf2(a2, a3);
        unsigned long long s45 = addf2(a4, a5), s67 = addf2(a6, a7);
        unsigned long long sp = addf2(addf2(s01, s23), addf2(s45, s67));
        float2 aa = unpack2(sp);
        float ssum = aa.x + aa.y;

        qj = mcur ? (ssum * sc) : (qj * rinv);
        sh_q[s & 1][j] = qj;
        ef = efn; fnx = fnx2; fnx2 = fnew;
        __syncthreads();
    }

    // ---- fwd = LSE_j(Cexp*ln2 + log qj + stop[j]) ----
    float v = (float)Cexp * 0.69314718055994531f + __logf(qj) + stop_t[j];
    {
        float m = v;
#pragma unroll
        for (int o = 16; o; o >>= 1) m = fmaxf(m, __shfl_xor_sync(0xffffffffu, m, o));
        if (l == 0) sh_wmax[wq] = m;
    }
    __syncthreads();
    float M = fmaxf(fmaxf(sh_wmax[0], sh_wmax[1]), fmaxf(sh_wmax[2], sh_wmax[3]));
    {
        float e = __expf(v - M);
#pragma unroll
        for (int o = 16; o; o >>= 1) e += __shfl_xor_sync(0xffffffffu, e, o);
        if (l == 0) sh_redf[wq] = e;
    }
    __syncthreads();
    float fwd = M + __logf(sh_redf[0] + sh_redf[1] + sh_redf[2] + sh_redf[3]);
    __syncthreads();   // protect sh_redf before reuse

    // ---- gold score (128 threads) ----
    float facc = 0.f, lacc = 0.f;
    for (int s = t; s < SS; s += NT) {
        float mk = (float)sh_mk[s];
        int tg = Tg[s];
        facc += Fb[(size_t)s * TT + tg] * mk;
        lacc += mk;
        if (s >= 1) facc += trans[Tg[s - 1] * TT + tg] * mk;
    }
#pragma unroll
    for (int o = 16; o; o >>= 1) {
        facc += __shfl_xor_sync(0xffffffffu, facc, o);
        lacc += __shfl_xor_sync(0xffffffffu, lacc, o);
    }
    if (l == 0) { sh_redf[wq] = facc; sh_redl[wq] = lacc; }
    __syncthreads();
    if (t == 0) {
        float fs = sh_redf[0] + sh_redf[1] + sh_redf[2] + sh_redf[3];
        float ls = sh_redl[0] + sh_redl[1] + sh_redl[2] + sh_redl[3];
        int len = (int)(ls + 0.5f);
        float gold = fs + start_t[Tg[0]] + stop_t[Tg[len - 1]];
        g_partial[b] = fwd - gold;
    }

    // ---- fused deterministic final reduction ----
    if (t == 0) {
        __threadfence();
        unsigned int old = atomicInc(&g_ctr, BB - 1);   // wraps to 0 each launch
        sh_last = (old == BB - 1) ? 1 : 0;
    }
    __syncthreads();
    if (sh_last) {
        if (t < BB) {
            float acc = __ldcg(&g_partial[t]);
#pragma unroll
            for (int o = 16; o; o >>= 1) acc += __shfl_xor_sync(0xffffffffu, acc, o);
            if ((t & 31) == 0) sh_redf[t >> 5] = acc;
        }
        __syncthreads();
        if (t == 0) out[0] = sh_redf[0] + sh_redf[1];
    }
}

extern "C" void kernel_launch(void* const* d_in, const int* in_sizes, int n_in,
                              void* d_out, int out_size) {
    const float* feats = (const float*)d_in[0];
    const int* mask = (const int*)d_in[1];
    const int* tags = (const int*)d_in[2];
    const float* trans = (const float*)d_in[3];
    const float* start_t = (const float*)d_in[4];
    const float* stop_t = (const float*)d_in[5];
    float* out = (float*)d_out;

    crf_kernel<<<BB, NT>>>(feats, mask, tags, trans, start_t, stop_t, out);
}

// round 14
// speedup vs baseline: 1.2353x; 1.2353x over previous
#include <cuda_runtime.h>
#include <math_constants.h>

#define BB 64
#define SS 512
#define TT 128
#define NT 128

__device__ float g_partial[BB];
__device__ unsigned int g_ctr = 0;

static __device__ __forceinline__ unsigned long long ffma2(unsigned long long a,
                                                           unsigned long long b,
                                                           unsigned long long c) {
    unsigned long long d;
    asm("fma.rn.f32x2 %0, %1, %2, %3;" : "=l"(d) : "l"(a), "l"(b), "l"(c));
    return d;
}
static __device__ __forceinline__ unsigned long long addf2(unsigned long long a,
                                                           unsigned long long b) {
    unsigned long long d;
    asm("add.rn.f32x2 %0, %1, %2;" : "=l"(d) : "l"(a), "l"(b));
    return d;
}
static __device__ __forceinline__ unsigned long long pack2(float x, float y) {
    unsigned long long d;
    asm("mov.b64 %0, {%1, %2};" : "=l"(d) : "f"(x), "f"(y));
    return d;
}
static __device__ __forceinline__ float2 unpack2(unsigned long long v) {
    float2 r;
    asm("mov.b64 {%0, %1}, %2;" : "=f"(r.x), "=f"(r.y) : "l"(v));
    return r;
}

__global__ __launch_bounds__(NT, 1)
void crf_kernel(const float* __restrict__ feats,
                const int* __restrict__ mask,
                const int* __restrict__ tags,
                const float* __restrict__ trans,
                const float* __restrict__ start_t,
                const float* __restrict__ stop_t,
                float* __restrict__ out)
{
    __shared__ __align__(16) float sh_q[2][TT];   // double-buffered linear partition
    __shared__ int sh_mk[SS];
    __shared__ float sh_wmax[4];
    __shared__ float sh_redf[4];
    __shared__ float sh_redl[4];
    __shared__ int sh_last;

    const int b = blockIdx.x;
    const int t = threadIdx.x;          // == column j
    const int j = t;
    const int wq = t >> 5;
    const int l = t & 31;
    const float* Fb = feats + (size_t)b * SS * TT;
    const int* Mk = mask + b * SS;
    const int* Tg = tags + b * SS;

    // preload mask into shared
    for (int s = t; s < SS; s += NT) sh_mk[s] = Mk[s];

    // E[i][j] = exp(trans[j][i]) for ALL i, this thread's column j
    unsigned long long e2[64];
#pragma unroll
    for (int k = 0; k < 64; k++) {
        float2 tv = *(const float2*)(trans + j * TT + 2 * k);
        e2[k] = pack2(__expf(tv.x), __expf(tv.y));
    }

    // ---- init: q0[j] = exp(F[0,j] + start[j]) ----
    float qj = __expf(Fb[j] + start_t[j]);
    sh_q[0][j] = qj;
    int Cexp = 0;
    float ef   = __expf(Fb[1 * TT + j]);  // exp(feat) for step 1
    float fnx  = Fb[2 * TT + j];          // raw feat for step 2
    float fnx2 = Fb[3 * TT + j];          // raw feat for step 3
    int mcur = Mk[1];                     // mask for step 1
    __syncthreads();

    // ---- sequential scan: all barrier-independent work hidden under the barrier ----
#pragma unroll 2
    for (int s = 1; s < SS; s++) {
        const int p = (s - 1) & 1;

        // post-barrier critical work ONLY: normalizer + matvec
        float q0p = sh_q[p][0];
        int e = (__float_as_int(q0p) >> 23) - 127;
        float rinv = __int_as_float((127 - e) << 23);
        Cexp += e;
        float sc = ef * rinv;

        // FULL matvec for column j — 32 broadcast LDS.128, 64 ffma2, 4 chains
        const ulonglong2* q8 = (const ulonglong2*)(&sh_q[p][0]);
        unsigned long long a0 = 0ull, a1 = 0ull, a2 = 0ull, a3 = 0ull;
#pragma unroll
        for (int k = 0; k < 32; k += 2) {
            ulonglong2 v0 = q8[k], v1 = q8[k + 1];
            a0 = ffma2(e2[2 * k + 0], v0.x, a0);
            a1 = ffma2(e2[2 * k + 1], v0.y, a1);
            a2 = ffma2(e2[2 * k + 2], v1.x, a2);
            a3 = ffma2(e2[2 * k + 3], v1.y, a3);
        }
        unsigned long long sp = addf2(addf2(a0, a1), addf2(a2, a3));
        float2 aa = unpack2(sp);
        float ssum = aa.x + aa.y;

        qj = mcur ? (ssum * sc) : (qj * rinv);
        sh_q[s & 1][j] = qj;

        // prefetch cluster for step s+1 — overlaps the barrier wait below
        float efn = __expf(fnx);
        int sp3 = (s + 3 < SS) ? (s + 3) : (SS - 1);
        float fnew = Fb[(size_t)sp3 * TT + j];
        int mnext = sh_mk[(s + 1 < SS) ? (s + 1) : (SS - 1)];
        ef = efn; fnx = fnx2; fnx2 = fnew; mcur = mnext;

        __syncthreads();
    }

    // ---- fwd = LSE_j(Cexp*ln2 + log qj + stop[j]) ----
    float v = (float)Cexp * 0.69314718055994531f + __logf(qj) + stop_t[j];
    {
        float m = v;
#pragma unroll
        for (int o = 16; o; o >>= 1) m = fmaxf(m, __shfl_xor_sync(0xffffffffu, m, o));
        if (l == 0) sh_wmax[wq] = m;
    }
    __syncthreads();
    float M = fmaxf(fmaxf(sh_wmax[0], sh_wmax[1]), fmaxf(sh_wmax[2], sh_wmax[3]));
    {
        float e = __expf(v - M);
#pragma unroll
        for (int o = 16; o; o >>= 1) e += __shfl_xor_sync(0xffffffffu, e, o);
        if (l == 0) sh_redf[wq] = e;
    }
    __syncthreads();
    float fwd = M + __logf(sh_redf[0] + sh_redf[1] + sh_redf[2] + sh_redf[3]);
    __syncthreads();   // protect sh_redf before reuse

    // ---- gold score (128 threads) ----
    float facc = 0.f, lacc = 0.f;
    for (int s = t; s < SS; s += NT) {
        float mk = (float)sh_mk[s];
        int tg = Tg[s];
        facc += Fb[(size_t)s * TT + tg] * mk;
        lacc += mk;
        if (s >= 1) facc += trans[Tg[s - 1] * TT + tg] * mk;
    }
#pragma unroll
    for (int o = 16; o; o >>= 1) {
        facc += __shfl_xor_sync(0xffffffffu, facc, o);
        lacc += __shfl_xor_sync(0xffffffffu, lacc, o);
    }
    if (l == 0) { sh_redf[wq] = facc; sh_redl[wq] = lacc; }
    __syncthreads();
    if (t == 0) {
        float fs = sh_redf[0] + sh_redf[1] + sh_redf[2] + sh_redf[3];
        float ls = sh_redl[0] + sh_redl[1] + sh_redl[2] + sh_redl[3];
        int len = (int)(ls + 0.5f);
        float gold = fs + start_t[Tg[0]] + stop_t[Tg[len - 1]];
        g_partial[b] = fwd - gold;
    }

    // ---- fused deterministic final reduction ----
    if (t == 0) {
        __threadfence();
        unsigned int old = atomicInc(&g_ctr, BB - 1);   // wraps to 0 each launch
        sh_last = (old == BB - 1) ? 1 : 0;
    }
    __syncthreads();
    if (sh_last) {
        if (t < BB) {
            float acc = __ldcg(&g_partial[t]);
#pragma unroll
            for (int o = 16; o; o >>= 1) acc += __shfl_xor_sync(0xffffffffu, acc, o);
            if ((t & 31) == 0) sh_redf[t >> 5] = acc;
        }
        __syncthreads();
        if (t == 0) out[0] = sh_redf[0] + sh_redf[1];
    }
}

extern "C" void kernel_launch(void* const* d_in, const int* in_sizes, int n_in,
                              void* d_out, int out_size) {
    const float* feats = (const float*)d_in[0];
    const int* mask = (const int*)d_in[1];
    const int* tags = (const int*)d_in[2];
    const float* trans = (const float*)d_in[3];
    const float* start_t = (const float*)d_in[4];
    const float* stop_t = (const float*)d_in[5];
    float* out = (float*)d_out;

    crf_kernel<<<BB, NT>>>(feats, mask, tags, trans, start_t, stop_t, out);
}

// round 15
// speedup vs baseline: 1.2517x; 1.0133x over previous
#include <cuda_runtime.h>
#include <math_constants.h>

#define BB 64
#define SS 512
#define TT 128
#define NT 128

__device__ float g_partial[BB];
__device__ unsigned int g_ctr = 0;

static __device__ __forceinline__ unsigned long long ffma2(unsigned long long a,
                                                           unsigned long long b,
                                                           unsigned long long c) {
    unsigned long long d;
    asm("fma.rn.f32x2 %0, %1, %2, %3;" : "=l"(d) : "l"(a), "l"(b), "l"(c));
    return d;
}
static __device__ __forceinline__ unsigned long long addf2(unsigned long long a,
                                                           unsigned long long b) {
    unsigned long long d;
    asm("add.rn.f32x2 %0, %1, %2;" : "=l"(d) : "l"(a), "l"(b));
    return d;
}
static __device__ __forceinline__ unsigned long long pack2(float x, float y) {
    unsigned long long d;
    asm("mov.b64 %0, {%1, %2};" : "=l"(d) : "f"(x), "f"(y));
    return d;
}
static __device__ __forceinline__ float2 unpack2(unsigned long long v) {
    float2 r;
    asm("mov.b64 {%0, %1}, %2;" : "=f"(r.x), "=f"(r.y) : "l"(v));
    return r;
}

__global__ __launch_bounds__(NT, 1)
void crf_kernel(const float* __restrict__ feats,
                const int* __restrict__ mask,
                const int* __restrict__ tags,
                const float* __restrict__ trans,
                const float* __restrict__ start_t,
                const float* __restrict__ stop_t,
                float* __restrict__ out)
{
    __shared__ __align__(16) float sh_q[2][TT];   // double-buffered linear partition
    __shared__ int sh_mk[SS];
    __shared__ float sh_wmax[4];
    __shared__ float sh_redf[4];
    __shared__ float sh_redl[4];
    __shared__ int sh_last;

    const int b = blockIdx.x;
    const int t = threadIdx.x;          // == column j
    const int j = t;
    const int wq = t >> 5;
    const int l = t & 31;
    const float* Fb = feats + (size_t)b * SS * TT;
    const int* Mk = mask + b * SS;
    const int* Tg = tags + b * SS;

    // preload mask into shared
    for (int s = t; s < SS; s += NT) sh_mk[s] = Mk[s];

    // E[i][j] = exp(trans[j][i]) for ALL i, this thread's column j
    unsigned long long e2[64];
#pragma unroll
    for (int k = 0; k < 64; k++) {
        float2 tv = *(const float2*)(trans + j * TT + 2 * k);
        e2[k] = pack2(__expf(tv.x), __expf(tv.y));
    }

    // ---- init: q0[j] = exp(F[0,j] + start[j]) ----
    float qj = __expf(Fb[j] + start_t[j]);
    sh_q[0][j] = qj;
    int Cexp = 0;
    float ef   = __expf(Fb[1 * TT + j]);  // exp(feat) for step 1
    float fnx  = Fb[2 * TT + j];          // raw feat for step 2
    float fnx2 = Fb[3 * TT + j];          // raw feat for step 3
    int mcur = Mk[1];                     // mask for step 1
    __syncthreads();

    // ---- sequential scan ----
#pragma unroll 4
    for (int s = 1; s < SS; s++) {
        const int p = (s - 1) & 1;

        // FULL matvec for column j — 32 broadcast LDS.128, 64 ffma2, 4 chains.
        // q[0] (the normalizer source) comes free from the low half of the
        // first load, so the rinv chain overlaps the FFMA stream entirely.
        const ulonglong2* q8 = (const ulonglong2*)(&sh_q[p][0]);
        ulonglong2 v0 = q8[0], v1 = q8[1];

        float q0p = unpack2(v0.x).x;                      // sh_q[p][0]
        int e = (__float_as_int(q0p) >> 23) - 127;
        float rinv = __int_as_float((127 - e) << 23);     // exact 2^{-e}
        Cexp += e;
        float sc = ef * rinv;

        unsigned long long a0 = 0ull, a1 = 0ull, a2 = 0ull, a3 = 0ull;
        a0 = ffma2(e2[0], v0.x, a0);
        a1 = ffma2(e2[1], v0.y, a1);
        a2 = ffma2(e2[2], v1.x, a2);
        a3 = ffma2(e2[3], v1.y, a3);
#pragma unroll
        for (int k = 2; k < 32; k += 2) {
            ulonglong2 w0 = q8[k], w1 = q8[k + 1];
            a0 = ffma2(e2[2 * k + 0], w0.x, a0);
            a1 = ffma2(e2[2 * k + 1], w0.y, a1);
            a2 = ffma2(e2[2 * k + 2], w1.x, a2);
            a3 = ffma2(e2[2 * k + 3], w1.y, a3);
        }
        unsigned long long sp = addf2(addf2(a0, a1), addf2(a2, a3));
        float2 aa = unpack2(sp);
        float ssum = aa.x + aa.y;

        qj = mcur ? (ssum * sc) : (qj * rinv);
        sh_q[s & 1][j] = qj;

        // prefetch cluster for step s+1 — overlaps the barrier wait below
        float efn = __expf(fnx);
        int sp3 = (s + 3 < SS) ? (s + 3) : (SS - 1);
        float fnew = Fb[(size_t)sp3 * TT + j];
        int mnext = sh_mk[(s + 1 < SS) ? (s + 1) : (SS - 1)];
        ef = efn; fnx = fnx2; fnx2 = fnew; mcur = mnext;

        __syncthreads();
    }

    // ---- fwd = LSE_j(Cexp*ln2 + log qj + stop[j]) ----
    float v = (float)Cexp * 0.69314718055994531f + __logf(qj) + stop_t[j];
    {
        float m = v;
#pragma unroll
        for (int o = 16; o; o >>= 1) m = fmaxf(m, __shfl_xor_sync(0xffffffffu, m, o));
        if (l == 0) sh_wmax[wq] = m;
    }
    __syncthreads();
    float M = fmaxf(fmaxf(sh_wmax[0], sh_wmax[1]), fmaxf(sh_wmax[2], sh_wmax[3]));
    {
        float e = __expf(v - M);
#pragma unroll
        for (int o = 16; o; o >>= 1) e += __shfl_xor_sync(0xffffffffu, e, o);
        if (l == 0) sh_redf[wq] = e;
    }
    __syncthreads();
    float fwd = M + __logf(sh_redf[0] + sh_redf[1] + sh_redf[2] + sh_redf[3]);
    __syncthreads();   // protect sh_redf before reuse

    // ---- gold score (128 threads) ----
    float facc = 0.f, lacc = 0.f;
    for (int s = t; s < SS; s += NT) {
        float mk = (float)sh_mk[s];
        int tg = Tg[s];
        facc += Fb[(size_t)s * TT + tg] * mk;
        lacc += mk;
        if (s >= 1) facc += trans[Tg[s - 1] * TT + tg] * mk;
    }
#pragma unroll
    for (int o = 16; o; o >>= 1) {
        facc += __shfl_xor_sync(0xffffffffu, facc, o);
        lacc += __shfl_xor_sync(0xffffffffu, lacc, o);
    }
    if (l == 0) { sh_redf[wq] = facc; sh_redl[wq] = lacc; }
    __syncthreads();
    if (t == 0) {
        float fs = sh_redf[0] + sh_redf[1] + sh_redf[2] + sh_redf[3];
        float ls = sh_redl[0] + sh_redl[1] + sh_redl[2] + sh_redl[3];
        int len = (int)(ls + 0.5f);
        float gold = fs + start_t[Tg[0]] + stop_t[Tg[len - 1]];
        g_partial[b] = fwd - gold;
    }

    // ---- fused deterministic final reduction ----
    if (t == 0) {
        __threadfence();
        unsigned int old = atomicInc(&g_ctr, BB - 1);   // wraps to 0 each launch
        sh_last = (old == BB - 1) ? 1 : 0;
    }
    __syncthreads();
    if (sh_last) {
        if (t < BB) {
            float acc = __ldcg(&g_partial[t]);
#pragma unroll
            for (int o = 16; o; o >>= 1) acc += __shfl_xor_sync(0xffffffffu, acc, o);
            if ((t & 31) == 0) sh_redf[t >> 5] = acc;
        }
        __syncthreads();
        if (t == 0) out[0] = sh_redf[0] + sh_redf[1];
    }
}

extern "C" void kernel_launch(void* const* d_in, const int* in_sizes, int n_in,
                              void* d_out, int out_size) {
    const float* feats = (const float*)d_in[0];
    const int* mask = (const int*)d_in[1];
    const int* tags = (const int*)d_in[2];
    const float* trans = (const float*)d_in[3];
    const float* start_t = (const float*)d_in[4];
    const float* stop_t = (const float*)d_in[5];
    float* out = (float*)d_out;

    crf_kernel<<<BB, NT>>>(feats, mask, tags, trans, start_t, stop_t, out);
}